// round 8
// baseline (speedup 1.0000x reference)
#include <cuda_runtime.h>
#include <cuda_fp16.h>
#include <cstdint>

#define DEV __device__ __forceinline__

namespace {
constexpr int NPTS = 131072;
constexpr int MT = 128;       // points per CTA
constexpr int THREADS = 288;  // 8 compute warps (2Mx4N, 64x64 tiles) + 1 producer warp
constexpr int CTH = 256;      // compute threads
constexpr int KC = 32;        // K chunk
constexpr int AS = 264;       // activation row stride (halves); 528B
constexpr int WS = 40;        // weight/feat row stride (halves); 80B
constexpr float TWO_PI = 6.2831853071795864769f;

constexpr int CH_H = 256 * WS;       // halves per weight chunk (10240)
constexpr uint32_t CH_B = CH_H * 2;  // 20480 bytes
constexpr int L0_CHUNKS = 17;        // K0 = 544 (515 padded)
constexpr int N_CHUNKS = L0_CHUNKS + 64;  // 81 flat chunks

// SMEM map (bytes)
constexpr int OFF_ACTA  = 0;                 // 67584
constexpr int OFF_ACTB  = 67584;             // 67584
constexpr int OFF_WRING = 135168;            // 3 * 20480
constexpr int OFF_UNION = 196608;            // L0: sx+sB | heads: Wc2+Wn2
constexpr int OFF_SX    = OFF_UNION;
constexpr int OFF_SB    = OFF_UNION + 2048;
constexpr int OFF_WC2   = OFF_UNION;
constexpr int OFF_WN2   = OFF_UNION + 3072;
constexpr int OFF_FEAT  = 201728;            // 2 * 10240
constexpr int OFF_BIAS  = 222208;            // 2 x 1024 (double-buffered)
constexpr int OFF_OUTAC = 224256;            // 2048
constexpr int OFF_FULL  = 226304;            // 3 x 8
constexpr int OFF_EMPTY = 226328;            // 3 x 8
constexpr int SMEM_BYTES = 226368;
}

// Weight images, flat: chunk i at g_Wt + i*CH_H. L0 = chunks 0..16, layer l = 17+8(l-1)..
__device__ __half g_Wt[(size_t)N_CHUNKS * CH_H];

// ---------------- helpers ----------------
DEV uint32_t smem_u32(const void* p) {
  uint32_t a;
  asm("{ .reg .u64 t; cvta.to.shared.u64 t, %1; cvt.u32.u64 %0, t; }" : "=r"(a) : "l"(p));
  return a;
}
#define MBAR_INIT(mb, c) \
  asm volatile("mbarrier.init.shared.b64 [%0], %1;" :: "r"(mb), "r"(c) : "memory")
#define MBAR_ARRIVE(mb) \
  asm volatile("mbarrier.arrive.shared.b64 _, [%0];" :: "r"(mb) : "memory")
#define MBAR_WAIT(mb, ph) do {                                                        \
  uint32_t _m = (mb), _p = (uint32_t)(ph), _d;                                        \
  asm volatile("{ .reg .pred p; mbarrier.try_wait.parity.acquire.cta.shared::cta.b64 p, [%1], %2; selp.b32 %0,1,0,p; }" \
               : "=r"(_d) : "r"(_m), "r"(_p) : "memory");                             \
  if (!_d) {                                                                          \
    asm volatile("{ .reg .pred P1; WL%=: mbarrier.try_wait.parity.acquire.cta.shared::cta.b64 P1, [%0], %1, 0x989680; @P1 bra.uni WD%=; bra.uni WL%=; WD%=: }" \
                 :: "r"(_m), "r"(_p) : "memory");                                     \
  }                                                                                   \
} while (0)

DEV void barsync() { asm volatile("bar.sync 1, 256;" ::: "memory"); }  // compute warps only

DEV void issue_chunk(uint32_t dst32, const void* src, uint32_t mbar) {
  asm volatile("mbarrier.arrive.expect_tx.shared.b64 _, [%0], %1;"
               :: "r"(mbar), "r"(CH_B) : "memory");
  asm volatile(
      "cp.async.bulk.shared::cta.global.mbarrier::complete_tx::bytes [%0], [%1], %2, [%3];"
      :: "r"(dst32), "l"(src), "r"(CH_B), "r"(mbar) : "memory");
}

DEV void ldsm4(uint32_t* r, uint32_t addr) {
  asm volatile("ldmatrix.sync.aligned.m8n8.x4.shared.b16 {%0,%1,%2,%3}, [%4];"
               : "=r"(r[0]), "=r"(r[1]), "=r"(r[2]), "=r"(r[3]) : "r"(addr));
}
DEV void mma16816(float* d, const uint32_t* a, uint32_t b0, uint32_t b1) {
  asm volatile(
      "mma.sync.aligned.m16n8k16.row.col.f32.f16.f16.f32 "
      "{%0,%1,%2,%3}, {%4,%5,%6,%7}, {%8,%9}, {%0,%1,%2,%3};\n"
      : "+f"(d[0]), "+f"(d[1]), "+f"(d[2]), "+f"(d[3])
      : "r"(a[0]), "r"(a[1]), "r"(a[2]), "r"(a[3]), "r"(b0), "r"(b1));
}
DEV float frelu(float v) { return fmaxf(v, 0.0f); }
DEV uint32_t pack2(float a, float b) {
  __half2 h = __floats2half2_rn(a, b);
  return *reinterpret_cast<uint32_t*>(&h);
}
// Cody-Waite pi reduction + polys; abs err ~4e-6, fast-math safe.
DEV void fsincos(float x, float& s, float& c) {
  float qf = rintf(x * 0.3183098861837907f);
  float r = fmaf(qf, -3.1414794921875f, x);
  r = fmaf(qf, -1.1315941810607910156e-4f, r);
  r = fmaf(qf, -1.9841872589410058936e-9f, r);
  float r2 = r * r;
  float sp = fmaf(r2, 2.7557319e-6f, -1.9841270e-4f);
  sp = fmaf(r2, sp, 8.3333333e-3f);
  sp = fmaf(r2, sp, -1.6666667e-1f);
  s = fmaf(r * r2, sp, r);
  float cp = fmaf(r2, -2.7557319e-7f, 2.4801587e-5f);
  cp = fmaf(r2, cp, -1.3888889e-3f);
  cp = fmaf(r2, cp, 4.1666667e-2f);
  cp = fmaf(r2, cp, -0.5f);
  c = fmaf(r2, cp, 1.0f);
  if (((int)qf) & 1) { s = -s; c = -c; }
}

// ---------------- prep: pack weights into SMEM-image layout ----------------
__global__ void prep_weights(const float* W0, const float* W1, const float* W2,
                             const float* W3, const float* W4, const float* Wc0,
                             const float* Wc1, const float* Wn0, const float* Wn1) {
  int e = blockIdx.x * blockDim.x + threadIdx.x;
  constexpr int TOTAL = N_CHUNKS * CH_H;
  if (e >= TOTAL) return;
  int chunk = e / CH_H, r = e % CH_H, n = r / WS, kk = r % WS;
  float v = 0.0f;
  if (kk < KC) {
    if (chunk < L0_CHUNKS) {
      int k = chunk * KC + kk;
      if (k < 515) v = W0[k * 256 + n];
    } else {
      int c2 = chunk - L0_CHUNKS;
      int l = c2 >> 3, k = (c2 & 7) * KC + kk;
      const float* Ws[8] = {W1, W2, W3, W4, Wc0, Wc1, Wn0, Wn1};
      v = Ws[l][k * 256 + n];
    }
  }
  g_Wt[e] = __float2half(v);
}

// ---------------- fused kernel ----------------
struct Params {
  const float *x, *B;
  const float *b0, *b1, *b2, *b3, *b4, *bc0, *bc1, *bc2, *bn0, *bn1, *bn2;
  const float *Wc2, *Wn2;
  const int* t;
  float* out;
};

struct Ctx {
  char* smem;
  uint32_t wring32, feat32, full32, empty32;
  int tid, wm, wn, lrow, lk, grp, qp, lane;
};

DEV void gen_feat(const Ctx& cx, int c, float tot) {
  const float* sx = (const float*)(cx.smem + OFF_SX);
  const float* sB = (const float*)(cx.smem + OFF_SB);
  __half* dst = (__half*)(cx.smem + OFF_FEAT + (c & 1) * 10240);
#pragma unroll
  for (int i = 0; i < 16; i++) {
    int idx = cx.tid + i * CTH;  // 128*32
    int m = idx >> 5, kk = idx & 31, kg = c * KC + kk;
    float v = 0.0f;
    if (kg < 3) {
      v = sx[m * 4 + kg];
    } else if (kg < 515) {
      int j = (kg < 259) ? (kg - 3) : (kg - 259);
      float px = sx[m * 4] * sB[j];
      px = fmaf(sx[m * 4 + 1], sB[256 + j], px);
      px = fmaf(sx[m * 4 + 2], sB[512 + j], px);
      float sv, cv;
      fsincos(px * TWO_PI, sv, cv);
      float a = fminf(fmaxf(tot - (float)j, 0.0f), 1.0f);
      v = ((kg < 259) ? sv : cv) * a;
    }
    dst[m * WS + kk] = __float2half(v);
  }
}

DEV void chunk_mma(const Ctx& cx, uint32_t aBase, int ast, int kb, uint32_t wslot,
                   float acc[4][8][4]) {
  const uint32_t aA0 = aBase + ((cx.wm * 64 + cx.lrow) * ast + kb + cx.lk) * 2;
  const uint32_t bA0 = wslot + ((cx.wn * 64 + cx.lrow) * WS + cx.lk) * 2;
#pragma unroll
  for (int ks = 0; ks < KC; ks += 16) {
    uint32_t a[4][4];
#pragma unroll
    for (int mt = 0; mt < 4; mt++) ldsm4(a[mt], aA0 + ks * 2 + mt * (16 * ast * 2));
#pragma unroll
    for (int np = 0; np < 4; np++) {
      uint32_t bb[4];
      ldsm4(bb, bA0 + ks * 2 + np * (16 * WS * 2));
#pragma unroll
      for (int mt = 0; mt < 4; mt++) {
        mma16816(acc[mt][2 * np],     a[mt], bb[0], bb[2]);
        mma16816(acc[mt][2 * np + 1], a[mt], bb[1], bb[3]);
      }
    }
  }
}

// MODE 0: act -> sOut. MODE 1: dot Wc2 -> outac. MODE 2: dot Wn2 -> outac.
template <int MODE>
__device__ __noinline__ void layerSq(const Ctx& cx, int base, const float* sbias,
                                     const __half* sIn, __half* sOut) {
  float* outac = (float*)(cx.smem + OFF_OUTAC);
  const uint32_t in32 = smem_u32(sIn);

  float acc[4][8][4];
#pragma unroll
  for (int a = 0; a < 4; a++)
#pragma unroll
    for (int b = 0; b < 8; b++)
#pragma unroll
      for (int d = 0; d < 4; d++) acc[a][b][d] = 0.0f;

  for (int c = 0; c < 8; c++) {
    const int g = base + c;
    const int s = g % 3;
    MBAR_WAIT(cx.full32 + s * 8, (g / 3) & 1);
    chunk_mma(cx, in32, AS, c * KC, cx.wring32 + s * CH_B, acc);
    if (cx.lane == 0) MBAR_ARRIVE(cx.empty32 + s * 8);
  }

  if (MODE == 0) {
#pragma unroll
    for (int mt = 0; mt < 4; mt++) {
      const int r0 = cx.wm * 64 + mt * 16 + cx.grp;
#pragma unroll
      for (int nt = 0; nt < 8; nt++) {
        const int col = cx.wn * 64 + nt * 8 + cx.qp * 2;
        float bx = sbias[col], by = sbias[col + 1];
        *(uint32_t*)(sOut + r0 * AS + col) =
            pack2(frelu(acc[mt][nt][0] + bx), frelu(acc[mt][nt][1] + by));
        *(uint32_t*)(sOut + (r0 + 8) * AS + col) =
            pack2(frelu(acc[mt][nt][2] + bx), frelu(acc[mt][nt][3] + by));
      }
    }
  } else {
    const float* sWc2 = (const float*)(cx.smem + OFF_WC2);
    const float* sWn2 = (const float*)(cx.smem + OFF_WN2);
    constexpr int NJ = (MODE == 1) ? 3 : 1;
    float part[4][2][NJ];
#pragma unroll
    for (int a = 0; a < 4; a++)
#pragma unroll
      for (int b = 0; b < 2; b++)
#pragma unroll
        for (int j = 0; j < NJ; j++) part[a][b][j] = 0.0f;
#pragma unroll
    for (int mt = 0; mt < 4; mt++)
#pragma unroll
      for (int nt = 0; nt < 8; nt++) {
        const int col = cx.wn * 64 + nt * 8 + cx.qp * 2;
        float bx = sbias[col], by = sbias[col + 1];
        float v0 = frelu(acc[mt][nt][0] + bx), v1 = frelu(acc[mt][nt][1] + by);
        float v2 = frelu(acc[mt][nt][2] + bx), v3 = frelu(acc[mt][nt][3] + by);
#pragma unroll
        for (int j = 0; j < NJ; j++) {
          float w0 = (MODE == 1) ? sWc2[col * 3 + j] : sWn2[col];
          float w1 = (MODE == 1) ? sWc2[(col + 1) * 3 + j] : sWn2[col + 1];
          part[mt][0][j] += v0 * w0 + v1 * w1;
          part[mt][1][j] += v2 * w0 + v3 * w1;
        }
      }
#pragma unroll
    for (int mt = 0; mt < 4; mt++)
#pragma unroll
      for (int rh = 0; rh < 2; rh++)
#pragma unroll
        for (int j = 0; j < NJ; j++) {
          float v = part[mt][rh][j];
          v += __shfl_xor_sync(0xffffffffu, v, 1);
          v += __shfl_xor_sync(0xffffffffu, v, 2);
          if (cx.qp == 0)
            atomicAdd(&outac[(cx.wm * 64 + mt * 16 + rh * 8 + cx.grp) * 4 + j], v);
        }
  }
  barsync();  // layer boundary: act handoff / outac visibility
}

__global__ void __launch_bounds__(THREADS, 1) fused_mlp(Params p) {
  extern __shared__ char smem[];
  Ctx cx;
  cx.smem = smem;
  cx.tid = threadIdx.x;
  cx.lane = cx.tid & 31;
  const int wid = cx.tid >> 5;
  cx.wm = (wid >> 2) & 1; cx.wn = wid & 3;
  cx.lrow = cx.lane & 15; cx.lk = (cx.lane >> 4) << 3;
  cx.grp = cx.lane >> 2; cx.qp = cx.lane & 3;
  cx.wring32 = smem_u32(smem + OFF_WRING);
  cx.feat32 = smem_u32(smem + OFF_FEAT);
  cx.full32 = smem_u32(smem + OFF_FULL);
  cx.empty32 = smem_u32(smem + OFF_EMPTY);

  const int m0 = blockIdx.x * MT;
  float* sx = (float*)(smem + OFF_SX);
  float* sB = (float*)(smem + OFF_SB);
  float* sb0 = (float*)(smem + OFF_BIAS);
  float* sb1 = (float*)(smem + OFF_BIAS + 1024);
  float* outac = (float*)(smem + OFF_OUTAC);
  __half* actA = (__half*)(smem + OFF_ACTA);
  __half* actB = (__half*)(smem + OFF_ACTB);

  if (cx.tid == 0) {
#pragma unroll
    for (int s = 0; s < 3; s++) {
      MBAR_INIT(cx.full32 + s * 8, 1);
      MBAR_INIT(cx.empty32 + s * 8, 8);
    }
  }
  for (int i = cx.tid; i < 384; i += THREADS) {
    int m = i / 3, d = i - m * 3;
    sx[m * 4 + d] = p.x[(m0 + m) * 3 + d];
  }
  for (int i = cx.tid; i < 768; i += THREADS) sB[i] = p.B[i];
  if (cx.tid < 256) { sb0[cx.tid] = p.b0[cx.tid]; sb1[cx.tid] = p.b1[cx.tid]; }
  for (int i = cx.tid; i < 512; i += THREADS) outac[i] = 0.0f;
  __syncthreads();  // all 288 threads; LAST full-block barrier

  if (wid == 8) {  // ---- producer warp ----
    if (cx.lane == 0) {
      for (int i = 0; i < N_CHUNKS; i++) {
        int s = i % 3;
        MBAR_WAIT(cx.empty32 + s * 8, 1 ^ ((i / 3) & 1));  // first waits pass
        issue_chunk(cx.wring32 + s * CH_B, g_Wt + (size_t)i * CH_H, cx.full32 + s * 8);
      }
    }
    return;
  }

  // ---- consumer (8 compute warps) ----
  int tbits = *p.t;
  float tval = (tbits >= 0 && tbits < (1 << 20)) ? (float)tbits : __int_as_float(tbits);
  const float tot = tval * (6000.0f / 512.0f);  // t / TAU

  // Layer 0: 17 chunks, on-the-fly features (double-buffered; per-chunk named barrier)
  {
    float acc[4][8][4];
#pragma unroll
    for (int a = 0; a < 4; a++)
#pragma unroll
      for (int b = 0; b < 8; b++)
#pragma unroll
        for (int d = 0; d < 4; d++) acc[a][b][d] = 0.0f;
    gen_feat(cx, 0, tot);
    for (int c = 0; c < L0_CHUNKS; c++) {
      barsync();  // feat buffer handoff (covers gen_feat(0) too)
      const int s = c % 3;
      MBAR_WAIT(cx.full32 + s * 8, (c / 3) & 1);
      chunk_mma(cx, cx.feat32 + (c & 1) * 10240, WS, 0, cx.wring32 + s * CH_B, acc);
      if (cx.lane == 0) MBAR_ARRIVE(cx.empty32 + s * 8);
      if (c + 1 < L0_CHUNKS) gen_feat(cx, c + 1, tot);
    }
    // epilogue -> actA (bias b0 in sb0)
#pragma unroll
    for (int mt = 0; mt < 4; mt++) {
      const int r0 = cx.wm * 64 + mt * 16 + cx.grp;
#pragma unroll
      for (int nt = 0; nt < 8; nt++) {
        const int col = cx.wn * 64 + nt * 8 + cx.qp * 2;
        float bx = sb0[col], by = sb0[col + 1];
        *(uint32_t*)(actA + r0 * AS + col) =
            pack2(frelu(acc[mt][nt][0] + bx), frelu(acc[mt][nt][1] + by));
        *(uint32_t*)(actA + (r0 + 8) * AS + col) =
            pack2(frelu(acc[mt][nt][2] + bx), frelu(acc[mt][nt][3] + by));
      }
    }
    barsync();
  }

  // overlay head-final weights (sx/sB/feat dead) + stage bias pipeline
  {
    float* sWc2 = (float*)(smem + OFF_WC2);
    float* sWn2 = (float*)(smem + OFF_WN2);
    for (int i = cx.tid; i < 768; i += CTH) sWc2[i] = p.Wc2[i];
    if (cx.tid < 256) sWn2[cx.tid] = p.Wn2[cx.tid];
  }

  if (cx.tid < 256) sb0[cx.tid] = p.b2[cx.tid];
  layerSq<0>(cx, 17, sb1, actA, actB);   // l1 (b1)
  if (cx.tid < 256) sb1[cx.tid] = p.b3[cx.tid];
  layerSq<0>(cx, 25, sb0, actB, actA);   // l2 (b2)
  if (cx.tid < 256) sb0[cx.tid] = p.b4[cx.tid];
  layerSq<0>(cx, 33, sb1, actA, actB);   // l3 (b3)
  if (cx.tid < 256) sb1[cx.tid] = p.bc0[cx.tid];
  layerSq<0>(cx, 41, sb0, actB, actA);   // l4 (b4) -> h in actA
  if (cx.tid < 256) sb0[cx.tid] = p.bc1[cx.tid];
  layerSq<0>(cx, 49, sb1, actA, actB);   // l5 (bc0)
  if (cx.tid < 256) sb1[cx.tid] = p.bn0[cx.tid];
  layerSq<1>(cx, 57, sb0, actB, nullptr);  // l6 (bc1), color dot
  for (int i = cx.tid; i < 384; i += CTH) {
    int m = i / 3, j = i - m * 3;
    float v = outac[m * 4 + j];
    outac[m * 4 + j] = 0.0f;  // read-side zero for displacement head
    p.out[(m0 + m) * 3 + j] = tanhf(v + p.bc2[j]) * 0.5f;
  }
  if (cx.tid < 256) sb0[cx.tid] = p.bn1[cx.tid];
  layerSq<0>(cx, 65, sb1, actA, actB);   // l7 (bn0), h intact in actA
  layerSq<2>(cx, 73, sb0, actB, nullptr);  // l8 (bn1), displacement dot
  if (cx.tid < 128)
    p.out[3 * NPTS + m0 + cx.tid] = tanhf(outac[cx.tid * 4] + p.bn2[0]) * 0.1f;
}

extern "C" void kernel_launch(void* const* d_in, const int* in_sizes, int n_in,
                              void* d_out, int out_size) {
  int i = 0;
  const float* x = (const float*)d_in[i++];
  const float* B = (const float*)d_in[i++];
  const void* tp = nullptr;
  if (in_sizes[2] == 1) tp = d_in[i++];  // dict order: t at index 2
  const float *W[11], *bias[11];
  for (int j = 0; j < 11; j++) {
    W[j] = (const float*)d_in[i++];
    bias[j] = (const float*)d_in[i++];
  }
  if (!tp && i < n_in) tp = d_in[i++];

  cudaFuncSetAttribute(fused_mlp, cudaFuncAttributeMaxDynamicSharedMemorySize, SMEM_BYTES);

  constexpr int TOTAL = N_CHUNKS * CH_H;
  prep_weights<<<(TOTAL + 255) / 256, 256>>>(W[0], W[1], W[2], W[3], W[4],
                                             W[5], W[6], W[8], W[9]);

  Params p;
  p.x = x; p.B = B;
  p.b0 = bias[0]; p.b1 = bias[1]; p.b2 = bias[2]; p.b3 = bias[3]; p.b4 = bias[4];
  p.bc0 = bias[5]; p.bc1 = bias[6]; p.bc2 = bias[7];
  p.bn0 = bias[8]; p.bn1 = bias[9]; p.bn2 = bias[10];
  p.Wc2 = W[7]; p.Wn2 = W[10];
  p.t = (const int*)tp;
  p.out = (float*)d_out;

  fused_mlp<<<NPTS / MT, THREADS, SMEM_BYTES>>>(p);
}

// round 9
// speedup vs baseline: 1.4078x; 1.4078x over previous
#include <cuda_runtime.h>
#include <cuda_fp16.h>
#include <cstdint>

#define DEV __device__ __forceinline__

namespace {
constexpr int NPTS = 131072;
constexpr int MT = 128;       // points per CTA
constexpr int THREADS = 544;  // 16 compute warps (4Mx4N) + 1 producer warp
constexpr int CTH = 512;      // compute threads
constexpr int KC = 32;        // K chunk
constexpr int AS = 264;       // activation row stride (halves); 528B
constexpr int WS = 40;        // weight/feat row stride (halves); 80B
constexpr float TWO_PI = 6.2831853071795864769f;

constexpr int CH_H = 256 * WS;       // halves per weight chunk (10240)
constexpr uint32_t CH_B = CH_H * 2;  // 20480 bytes
constexpr int L0_CHUNKS = 17;        // K0 = 544 (515 padded)
constexpr int N_CHUNKS = L0_CHUNKS + 64;  // 81 flat chunks

// SMEM map (bytes)
constexpr int OFF_ACTA  = 0;                 // 67584
constexpr int OFF_ACTB  = 67584;             // 67584
constexpr int OFF_WRING = 135168;            // 3 * 20480
constexpr int OFF_UNION = 196608;            // L0: sx+sB | heads: Wc2+Wn2
constexpr int OFF_SX    = OFF_UNION;
constexpr int OFF_SB    = OFF_UNION + 2048;
constexpr int OFF_WC2   = OFF_UNION;
constexpr int OFF_WN2   = OFF_UNION + 3072;
constexpr int OFF_FEAT  = 201728;            // 2 * 10240
constexpr int OFF_BIAS  = 222208;            // 2 x 1024 (double-buffered)
constexpr int OFF_OUTAC = 224256;            // 2048
constexpr int OFF_FULL  = 226304;            // 3 x 8
constexpr int OFF_EMPTY = 226328;            // 3 x 8
constexpr int SMEM_BYTES = 226368;
}

// Weight images, flat: chunk i at g_Wt + i*CH_H. L0 = chunks 0..16, layer l = 17+8(l-1)..
__device__ __half g_Wt[(size_t)N_CHUNKS * CH_H];

// ---------------- helpers ----------------
DEV uint32_t smem_u32(const void* p) {
  uint32_t a;
  asm("{ .reg .u64 t; cvta.to.shared.u64 t, %1; cvt.u32.u64 %0, t; }" : "=r"(a) : "l"(p));
  return a;
}
#define MBAR_INIT(mb, c) \
  asm volatile("mbarrier.init.shared.b64 [%0], %1;" :: "r"(mb), "r"(c) : "memory")
#define MBAR_ARRIVE(mb) \
  asm volatile("mbarrier.arrive.shared.b64 _, [%0];" :: "r"(mb) : "memory")
#define MBAR_WAIT(mb, ph) do {                                                        \
  uint32_t _m = (mb), _p = (uint32_t)(ph), _d;                                        \
  asm volatile("{ .reg .pred p; mbarrier.try_wait.parity.acquire.cta.shared::cta.b64 p, [%1], %2; selp.b32 %0,1,0,p; }" \
               : "=r"(_d) : "r"(_m), "r"(_p) : "memory");                             \
  if (!_d) {                                                                          \
    asm volatile("{ .reg .pred P1; WL%=: mbarrier.try_wait.parity.acquire.cta.shared::cta.b64 P1, [%0], %1, 0x989680; @P1 bra.uni WD%=; bra.uni WL%=; WD%=: }" \
                 :: "r"(_m), "r"(_p) : "memory");                                     \
  }                                                                                   \
} while (0)

DEV void barsync() { asm volatile("bar.sync 1, 512;" ::: "memory"); }  // compute warps only

DEV void issue_chunk(uint32_t dst32, const void* src, uint32_t mbar) {
  asm volatile("mbarrier.arrive.expect_tx.shared.b64 _, [%0], %1;"
               :: "r"(mbar), "r"(CH_B) : "memory");
  asm volatile(
      "cp.async.bulk.shared::cta.global.mbarrier::complete_tx::bytes [%0], [%1], %2, [%3];"
      :: "r"(dst32), "l"(src), "r"(CH_B), "r"(mbar) : "memory");
}

DEV void ldsm4(uint32_t* r, uint32_t addr) {
  asm volatile("ldmatrix.sync.aligned.m8n8.x4.shared.b16 {%0,%1,%2,%3}, [%4];"
               : "=r"(r[0]), "=r"(r[1]), "=r"(r[2]), "=r"(r[3]) : "r"(addr));
}
DEV void mma16816(float* d, const uint32_t* a, uint32_t b0, uint32_t b1) {
  asm volatile(
      "mma.sync.aligned.m16n8k16.row.col.f32.f16.f16.f32 "
      "{%0,%1,%2,%3}, {%4,%5,%6,%7}, {%8,%9}, {%0,%1,%2,%3};\n"
      : "+f"(d[0]), "+f"(d[1]), "+f"(d[2]), "+f"(d[3])
      : "r"(a[0]), "r"(a[1]), "r"(a[2]), "r"(a[3]), "r"(b0), "r"(b1));
}
DEV float frelu(float v) { return fmaxf(v, 0.0f); }
DEV uint32_t pack2(float a, float b) {
  __half2 h = __floats2half2_rn(a, b);
  return *reinterpret_cast<uint32_t*>(&h);
}

// ---------------- prep: pack weights into SMEM-image layout ----------------
__global__ void prep_weights(const float* W0, const float* W1, const float* W2,
                             const float* W3, const float* W4, const float* Wc0,
                             const float* Wc1, const float* Wn0, const float* Wn1) {
  int e = blockIdx.x * blockDim.x + threadIdx.x;
  constexpr int TOTAL = N_CHUNKS * CH_H;
  if (e >= TOTAL) return;
  int chunk = e / CH_H, r = e % CH_H, n = r / WS, kk = r % WS;
  float v = 0.0f;
  if (kk < KC) {
    if (chunk < L0_CHUNKS) {
      int k = chunk * KC + kk;
      if (k < 515) v = W0[k * 256 + n];
    } else {
      int c2 = chunk - L0_CHUNKS;
      int l = c2 >> 3, k = (c2 & 7) * KC + kk;
      const float* Ws[8] = {W1, W2, W3, W4, Wc0, Wc1, Wn0, Wn1};
      v = Ws[l][k * 256 + n];
    }
  }
  g_Wt[e] = __float2half(v);
}

// ---------------- fused kernel ----------------
struct Params {
  const float *x, *B;
  const float *b0, *b1, *b2, *b3, *b4, *bc0, *bc1, *bc2, *bn0, *bn1, *bn2;
  const float *Wc2, *Wn2;
  const int* t;
  float* out;
};

struct Ctx {
  char* smem;
  uint32_t wring32, feat32, full32, empty32;
  int tid, wm, wn, lrow, lk, grp, qp, lane;
};

// Layer-0 feature chunk: per-thread column kk is FIXED -> hoist B row, alpha,
// sin/cos select out of the m-loop. Cody-Waite pi-reduction (exact) + MUFU
// sin/cos on reduced |r|<=pi/2 (full approx accuracy there).
DEV void gen_feat(const Ctx& cx, int c, float tot) {
  const float* sx = (const float*)(cx.smem + OFF_SX);
  const float* sB = (const float*)(cx.smem + OFF_SB);
  __half* dst = (__half*)(cx.smem + OFF_FEAT + (c & 1) * 10240);
  const int kk = cx.tid & 31;
  const int mb = cx.tid >> 5;  // m = mb + i*16
  const int kg = c * KC + kk;
  if (kg >= 3 && kg < 515) {
    const bool issin = kg < 259;
    const int j = issin ? (kg - 3) : (kg - 259);
    const float Bx = sB[j], By = sB[256 + j], Bz = sB[512 + j];
    const float a = fminf(fmaxf(tot - (float)j, 0.0f), 1.0f);
#pragma unroll
    for (int i = 0; i < 8; i++) {
      const int m = mb + i * 16;
      float px = sx[m * 4] * Bx;
      px = fmaf(sx[m * 4 + 1], By, px);
      px = fmaf(sx[m * 4 + 2], Bz, px);
      float arg = px * TWO_PI;
      float qf = rintf(arg * 0.3183098861837907f);  // 1/pi
      float r = fmaf(qf, -3.1414794921875f, arg);
      r = fmaf(qf, -1.1315941810607910156e-4f, r);
      r = fmaf(qf, -1.9841872589410058936e-9f, r);
      float v = issin ? __sinf(r) : __cosf(r);
      if (((int)qf) & 1) v = -v;
      dst[m * WS + kk] = __float2half(v * a);
    }
  } else {
    const bool isx = (kg < 3);
#pragma unroll
    for (int i = 0; i < 8; i++) {
      const int m = mb + i * 16;
      dst[m * WS + kk] = __float2half(isx ? sx[m * 4 + kg] : 0.0f);
    }
  }
}

DEV void chunk_mma(const Ctx& cx, uint32_t aBase, int ast, int kb, uint32_t wslot,
                   float acc[2][8][4]) {
  const uint32_t aA0 = aBase + ((cx.wm * 32 + cx.lrow) * ast + kb + cx.lk) * 2;
  const uint32_t bA0 = wslot + ((cx.wn * 64 + cx.lrow) * WS + cx.lk) * 2;
#pragma unroll
  for (int ks = 0; ks < KC; ks += 16) {
    uint32_t a0[4], a1[4];
    ldsm4(a0, aA0 + ks * 2);
    ldsm4(a1, aA0 + ks * 2 + 16 * ast * 2);
#pragma unroll
    for (int np = 0; np < 4; np++) {
      uint32_t bb[4];
      ldsm4(bb, bA0 + ks * 2 + np * (16 * WS * 2));
      mma16816(acc[0][2 * np],     a0, bb[0], bb[2]);
      mma16816(acc[0][2 * np + 1], a0, bb[1], bb[3]);
      mma16816(acc[1][2 * np],     a1, bb[0], bb[2]);
      mma16816(acc[1][2 * np + 1], a1, bb[1], bb[3]);
    }
  }
}

// MODE 0: act -> sOut. MODE 1: dot Wc2 -> outac. MODE 2: dot Wn2 -> outac.
template <int MODE>
__device__ __noinline__ void layerSq(const Ctx& cx, int base, const float* sbias,
                                     const __half* sIn, __half* sOut) {
  float* outac = (float*)(cx.smem + OFF_OUTAC);
  const uint32_t in32 = smem_u32(sIn);

  float acc[2][8][4];
#pragma unroll
  for (int a = 0; a < 2; a++)
#pragma unroll
    for (int b = 0; b < 8; b++)
#pragma unroll
      for (int d = 0; d < 4; d++) acc[a][b][d] = 0.0f;

  for (int c = 0; c < 8; c++) {
    const int g = base + c;
    const int s = g % 3;
    MBAR_WAIT(cx.full32 + s * 8, (g / 3) & 1);
    chunk_mma(cx, in32, AS, c * KC, cx.wring32 + s * CH_B, acc);
    if (cx.lane == 0) MBAR_ARRIVE(cx.empty32 + s * 8);
  }

  if (MODE == 0) {
#pragma unroll
    for (int mt = 0; mt < 2; mt++) {
      const int r0 = cx.wm * 32 + mt * 16 + cx.grp;
#pragma unroll
      for (int nt = 0; nt < 8; nt++) {
        const int col = cx.wn * 64 + nt * 8 + cx.qp * 2;
        float bx = sbias[col], by = sbias[col + 1];
        *(uint32_t*)(sOut + r0 * AS + col) =
            pack2(frelu(acc[mt][nt][0] + bx), frelu(acc[mt][nt][1] + by));
        *(uint32_t*)(sOut + (r0 + 8) * AS + col) =
            pack2(frelu(acc[mt][nt][2] + bx), frelu(acc[mt][nt][3] + by));
      }
    }
  } else {
    const float* sWc2 = (const float*)(cx.smem + OFF_WC2);
    const float* sWn2 = (const float*)(cx.smem + OFF_WN2);
    constexpr int NJ = (MODE == 1) ? 3 : 1;
    float part[2][2][NJ];
#pragma unroll
    for (int a = 0; a < 2; a++)
#pragma unroll
      for (int b = 0; b < 2; b++)
#pragma unroll
        for (int j = 0; j < NJ; j++) part[a][b][j] = 0.0f;
#pragma unroll
    for (int mt = 0; mt < 2; mt++)
#pragma unroll
      for (int nt = 0; nt < 8; nt++) {
        const int col = cx.wn * 64 + nt * 8 + cx.qp * 2;
        float bx = sbias[col], by = sbias[col + 1];
        float v0 = frelu(acc[mt][nt][0] + bx), v1 = frelu(acc[mt][nt][1] + by);
        float v2 = frelu(acc[mt][nt][2] + bx), v3 = frelu(acc[mt][nt][3] + by);
#pragma unroll
        for (int j = 0; j < NJ; j++) {
          float w0 = (MODE == 1) ? sWc2[col * 3 + j] : sWn2[col];
          float w1 = (MODE == 1) ? sWc2[(col + 1) * 3 + j] : sWn2[col + 1];
          part[mt][0][j] += v0 * w0 + v1 * w1;
          part[mt][1][j] += v2 * w0 + v3 * w1;
        }
      }
#pragma unroll
    for (int mt = 0; mt < 2; mt++)
#pragma unroll
      for (int rh = 0; rh < 2; rh++)
#pragma unroll
        for (int j = 0; j < NJ; j++) {
          float v = part[mt][rh][j];
          v += __shfl_xor_sync(0xffffffffu, v, 1);
          v += __shfl_xor_sync(0xffffffffu, v, 2);
          if (cx.qp == 0)
            atomicAdd(&outac[(cx.wm * 32 + mt * 16 + rh * 8 + cx.grp) * 4 + j], v);
        }
  }
  barsync();  // layer boundary: act handoff / outac visibility
}

__global__ void __launch_bounds__(THREADS, 1) fused_mlp(Params p) {
  extern __shared__ char smem[];
  Ctx cx;
  cx.smem = smem;
  cx.tid = threadIdx.x;
  cx.lane = cx.tid & 31;
  const int wid = cx.tid >> 5;
  cx.wm = (wid >> 2) & 3; cx.wn = wid & 3;
  cx.lrow = cx.lane & 15; cx.lk = (cx.lane >> 4) << 3;
  cx.grp = cx.lane >> 2; cx.qp = cx.lane & 3;
  cx.wring32 = smem_u32(smem + OFF_WRING);
  cx.feat32 = smem_u32(smem + OFF_FEAT);
  cx.full32 = smem_u32(smem + OFF_FULL);
  cx.empty32 = smem_u32(smem + OFF_EMPTY);

  const int m0 = blockIdx.x * MT;
  float* sx = (float*)(smem + OFF_SX);
  float* sB = (float*)(smem + OFF_SB);
  float* sb0 = (float*)(smem + OFF_BIAS);
  float* sb1 = (float*)(smem + OFF_BIAS + 1024);
  float* outac = (float*)(smem + OFF_OUTAC);
  __half* actA = (__half*)(smem + OFF_ACTA);
  __half* actB = (__half*)(smem + OFF_ACTB);

  if (cx.tid == 0) {
#pragma unroll
    for (int s = 0; s < 3; s++) {
      MBAR_INIT(cx.full32 + s * 8, 1);
      MBAR_INIT(cx.empty32 + s * 8, 16);
    }
  }
  if (cx.tid < 384) {
    int m = cx.tid / 3, d = cx.tid - m * 3;
    sx[m * 4 + d] = p.x[(m0 + m) * 3 + d];
  }
  for (int i = cx.tid; i < 768; i += THREADS) sB[i] = p.B[i];
  if (cx.tid < 256) { sb0[cx.tid] = p.b0[cx.tid]; sb1[cx.tid] = p.b1[cx.tid]; }
  if (cx.tid < CTH) outac[cx.tid] = 0.0f;
  __syncthreads();  // all 544 threads; LAST full-block barrier

  if (wid == 16) {  // ---- producer warp ----
    if (cx.lane == 0) {
      for (int i = 0; i < N_CHUNKS; i++) {
        int s = i % 3;
        MBAR_WAIT(cx.empty32 + s * 8, 1 ^ ((i / 3) & 1));  // first waits pass
        issue_chunk(cx.wring32 + s * CH_B, g_Wt + (size_t)i * CH_H, cx.full32 + s * 8);
      }
    }
    return;
  }

  // ---- consumer (16 compute warps) ----
  int tbits = *p.t;
  float tval = (tbits >= 0 && tbits < (1 << 20)) ? (float)tbits : __int_as_float(tbits);
  const float tot = tval * (6000.0f / 512.0f);  // t / TAU

  // Layer 0: 17 chunks, on-the-fly features (double-buffered; per-chunk named barrier)
  {
    float acc[2][8][4];
#pragma unroll
    for (int a = 0; a < 2; a++)
#pragma unroll
      for (int b = 0; b < 8; b++)
#pragma unroll
        for (int d = 0; d < 4; d++) acc[a][b][d] = 0.0f;
    gen_feat(cx, 0, tot);
    for (int c = 0; c < L0_CHUNKS; c++) {
      barsync();  // feat buffer handoff (covers gen_feat(0) too)
      const int s = c % 3;
      MBAR_WAIT(cx.full32 + s * 8, (c / 3) & 1);
      chunk_mma(cx, cx.feat32 + (c & 1) * 10240, WS, 0, cx.wring32 + s * CH_B, acc);
      if (cx.lane == 0) MBAR_ARRIVE(cx.empty32 + s * 8);
      if (c + 1 < L0_CHUNKS) gen_feat(cx, c + 1, tot);
    }
    // epilogue -> actA (bias b0 in sb0)
#pragma unroll
    for (int mt = 0; mt < 2; mt++) {
      const int r0 = cx.wm * 32 + mt * 16 + cx.grp;
#pragma unroll
      for (int nt = 0; nt < 8; nt++) {
        const int col = cx.wn * 64 + nt * 8 + cx.qp * 2;
        float bx = sb0[col], by = sb0[col + 1];
        *(uint32_t*)(actA + r0 * AS + col) =
            pack2(frelu(acc[mt][nt][0] + bx), frelu(acc[mt][nt][1] + by));
        *(uint32_t*)(actA + (r0 + 8) * AS + col) =
            pack2(frelu(acc[mt][nt][2] + bx), frelu(acc[mt][nt][3] + by));
      }
    }
    barsync();
  }

  // overlay head-final weights (sx/sB/feat dead) + stage bias pipeline
  {
    float* sWc2 = (float*)(smem + OFF_WC2);
    float* sWn2 = (float*)(smem + OFF_WN2);
    for (int i = cx.tid; i < 768; i += CTH) sWc2[i] = p.Wc2[i];
    if (cx.tid < 256) sWn2[cx.tid] = p.Wn2[cx.tid];
  }

  if (cx.tid < 256) sb0[cx.tid] = p.b2[cx.tid];
  layerSq<0>(cx, 17, sb1, actA, actB);   // l1 (b1)
  if (cx.tid < 256) sb1[cx.tid] = p.b3[cx.tid];
  layerSq<0>(cx, 25, sb0, actB, actA);   // l2 (b2)
  if (cx.tid < 256) sb0[cx.tid] = p.b4[cx.tid];
  layerSq<0>(cx, 33, sb1, actA, actB);   // l3 (b3)
  if (cx.tid < 256) sb1[cx.tid] = p.bc0[cx.tid];
  layerSq<0>(cx, 41, sb0, actB, actA);   // l4 (b4) -> h in actA
  if (cx.tid < 256) sb0[cx.tid] = p.bc1[cx.tid];
  layerSq<0>(cx, 49, sb1, actA, actB);   // l5 (bc0)
  if (cx.tid < 256) sb1[cx.tid] = p.bn0[cx.tid];
  layerSq<1>(cx, 57, sb0, actB, nullptr);  // l6 (bc1), color dot
  if (cx.tid < 384) {
    int m = cx.tid / 3, j = cx.tid - m * 3;
    float v = outac[m * 4 + j];
    outac[m * 4 + j] = 0.0f;  // read-side zero for displacement head
    p.out[(m0 + m) * 3 + j] = tanhf(v + p.bc2[j]) * 0.5f;
  }
  if (cx.tid < 256) sb0[cx.tid] = p.bn1[cx.tid];
  layerSq<0>(cx, 65, sb1, actA, actB);   // l7 (bn0), h intact in actA
  layerSq<2>(cx, 73, sb0, actB, nullptr);  // l8 (bn1), displacement dot
  if (cx.tid < 128)
    p.out[3 * NPTS + m0 + cx.tid] = tanhf(outac[cx.tid * 4] + p.bn2[0]) * 0.1f;
}

extern "C" void kernel_launch(void* const* d_in, const int* in_sizes, int n_in,
                              void* d_out, int out_size) {
  int i = 0;
  const float* x = (const float*)d_in[i++];
  const float* B = (const float*)d_in[i++];
  const void* tp = nullptr;
  if (in_sizes[2] == 1) tp = d_in[i++];  // dict order: t at index 2
  const float *W[11], *bias[11];
  for (int j = 0; j < 11; j++) {
    W[j] = (const float*)d_in[i++];
    bias[j] = (const float*)d_in[i++];
  }
  if (!tp && i < n_in) tp = d_in[i++];

  cudaFuncSetAttribute(fused_mlp, cudaFuncAttributeMaxDynamicSharedMemorySize, SMEM_BYTES);

  constexpr int TOTAL = N_CHUNKS * CH_H;
  prep_weights<<<(TOTAL + 255) / 256, 256>>>(W[0], W[1], W[2], W[3], W[4],
                                             W[5], W[6], W[8], W[9]);

  Params p;
  p.x = x; p.B = B;
  p.b0 = bias[0]; p.b1 = bias[1]; p.b2 = bias[2]; p.b3 = bias[3]; p.b4 = bias[4];
  p.bc0 = bias[5]; p.bc1 = bias[6]; p.bc2 = bias[7];
  p.bn0 = bias[8]; p.bn1 = bias[9]; p.bn2 = bias[10];
  p.Wc2 = W[7]; p.Wn2 = W[10];
  p.t = (const int*)tp;
  p.out = (float*)d_out;

  fused_mlp<<<NPTS / MT, THREADS, SMEM_BYTES>>>(p);
}